// round 14
// baseline (speedup 1.0000x reference)
#include <cuda_runtime.h>

// ---------------------------------------------------------------------------
// GraphSAGE 2-layer: N=100000 nodes, E=1.6M edges, 128 -> 128(relu) -> 64
// Aggregation AFTER the linear map (linearity of mean):
//   mean(h[src]) @ W_l == mean((h@W_l)[src]).
//
// BISECT LOG:
//  - builds with atomics (float or int) faulted with 717 InvalidAddressSpace
//  - atomic-free merge-sort build EXECUTED but rel_err=0.54 reading
//    edge_index as int64 -> edge_index is actually int32 (JAX x64 disabled).
// This build: edge_index read as int32. No atomics, no shfl anywhere.
// ---------------------------------------------------------------------------

#define MAXN 100000
#define MAXE 1600000
#define EID_BITS 21
#define EID_MASK ((1u << EID_BITS) - 1u)   // 2^21-1 = 2097151 > MAXE

__device__ float g_y[MAXN * 128];     // x @ W_l1
__device__ float g_agg1[MAXN * 128];  // gathered sum of g_y
__device__ float g_h[MAXN * 128];     // relu layer-1 output
__device__ float g_z[MAXN * 64];     // h @ W_l2
__device__ float g_agg2[MAXN * 64];  // gathered sum of g_z
__device__ float g_deg[MAXN];
__device__ unsigned long long g_keyA[MAXE];
__device__ unsigned long long g_keyB[MAXE];
__device__ int g_off[MAXN + 1];
__device__ int g_csr_src[MAXE];

// ---------------------------------------------------------------------------
// key[e] = (dst << 21) | e  — unique, lexicographic (dst, edge_id)
__global__ void init_keys_kernel(const int* __restrict__ ei,
                                 unsigned long long* __restrict__ key, int E) {
    int e = blockIdx.x * blockDim.x + threadIdx.x;
    if (e < E) {
        unsigned long long d = (unsigned long long)(unsigned int)ei[E + e];
        key[e] = (d << EID_BITS) | (unsigned long long)e;
    }
}

// One merge-path pass: merge adjacent sorted runs of length W.
// Each thread places its own element via binary search in the partner run.
// Keys are unique -> strict lower_bound works for both sides.
__global__ void merge_pass_kernel(const unsigned long long* __restrict__ in,
                                  unsigned long long* __restrict__ out,
                                  int E, int W) {
    int i = blockIdx.x * blockDim.x + threadIdx.x;
    if (i >= E) return;
    int pairStart = (i / (2 * W)) * (2 * W);
    int r = i - pairStart;
    unsigned long long k = in[i];
    if (r < W) {
        // element of run A; partner run B = [pairStart+W, min(pairStart+2W,E))
        int lo = pairStart + W;
        int hi = pairStart + 2 * W;
        if (lo > E) lo = E;
        if (hi > E) hi = E;
        int b0 = lo;
        while (lo < hi) {
            int mid = (lo + hi) >> 1;
            if (in[mid] < k) lo = mid + 1; else hi = mid;
        }
        out[pairStart + r + (lo - b0)] = k;
    } else {
        // element of run B; partner run A = [pairStart, pairStart+W) (full)
        int lo = pairStart;
        int hi = pairStart + W;
        while (lo < hi) {
            int mid = (lo + hi) >> 1;
            if (in[mid] < k) lo = mid + 1; else hi = mid;
        }
        out[pairStart + (r - W) + (lo - pairStart)] = k;
    }
}

// off[n] = first position in sorted keys with dst >= n  (n in [0, M])
__global__ void bounds_kernel(const unsigned long long* __restrict__ keys,
                              int* __restrict__ off, int E, int M) {
    int n = blockIdx.x * blockDim.x + threadIdx.x;
    if (n > M) return;
    unsigned long long target = ((unsigned long long)n) << EID_BITS;
    int lo = 0, hi = E;
    while (lo < hi) {
        int mid = (lo + hi) >> 1;
        if (keys[mid] < target) lo = mid + 1; else hi = mid;
    }
    off[n] = lo;
}

__global__ void deg_kernel(const int* __restrict__ off,
                           float* __restrict__ degf, int M) {
    int n = blockIdx.x * blockDim.x + threadIdx.x;
    if (n < M) degf[n] = (float)(off[n + 1] - off[n]);
}

// csr_src[j] = src of the edge encoded in sorted key j
__global__ void extract_kernel(const unsigned long long* __restrict__ keys,
                               const int* __restrict__ ei,
                               int* __restrict__ csr_src, int E) {
    int j = blockIdx.x * blockDim.x + threadIdx.x;
    if (j < E) {
        int eid = (int)(keys[j] & EID_MASK);
        csr_src[j] = ei[eid];
    }
}

// Warp-cooperative gather: LPN = CH/4 lanes cover one node (float4 per lane).
// CH=128 -> 1 node/warp; CH=64 -> 2 nodes/warp. csr_src load is uniform
// within the lane group (broadcast); feature loads are LDG.128 coalesced.
// Serial j-loop keeps summation order deterministic per node.
template <int CH>
__global__ void gather_kernel(const float* __restrict__ feat,
                              const int* __restrict__ csr_src,
                              const int* __restrict__ off,
                              float* __restrict__ agg, int M) {
    constexpr int LPN = CH / 4;    // lanes per node (32 or 16)
    constexpr int NPW = 32 / LPN;  // nodes per warp (1 or 2)
    const int gwarp = (blockIdx.x * blockDim.x + threadIdx.x) >> 5;
    const int lane = threadIdx.x & 31;
    const int n = gwarp * NPW + lane / LPN;
    if (n >= M) return;
    const int c = (lane % LPN) * 4;
    const int beg = off[n], end = off[n + 1];
    float4 acc = make_float4(0.f, 0.f, 0.f, 0.f);
#pragma unroll 4
    for (int j = beg; j < end; j++) {
        int s = csr_src[j];
        float4 v = *(const float4*)&feat[s * CH + c];
        acc.x += v.x; acc.y += v.y; acc.z += v.z; acc.w += v.w;
    }
    *(float4*)&agg[n * CH + c] = acc;
}

// ---------------------------------------------------------------------------
// Tiled SGEMM: C[M,BN] = A[M,128] @ W[128,BN]  (+ optional fused SAGE epilogue:
//   C = acc + agg[row]*inv_deg(row) + bias, optional relu)
// BM=128, BK=32, 256 threads, thread tile 8 x (BN/16).
// ---------------------------------------------------------------------------
template <int BN, bool EPI, bool RELU>
__global__ __launch_bounds__(256, 2)
void gemm128(const float* __restrict__ A, const float* __restrict__ W,
             const float* __restrict__ agg, const float* __restrict__ deg,
             const float* __restrict__ bias, float* __restrict__ C, int M) {
    constexpr int BM = 128, BK = 32, K = 128;
    constexpr int TM = 8;
    constexpr int TN = BN / 16;  // 8 (BN=128) or 4 (BN=64)

    __shared__ __align__(16) float As[BK][BM + 4];  // transposed A tile, padded
    __shared__ __align__(16) float Bs[BK][BN];

    const int tid = threadIdx.x;
    const int tx = tid % 16;  // column group
    const int ty = tid / 16;  // row group
    const int row0 = blockIdx.x * BM;

    float acc[TM][TN];
#pragma unroll
    for (int i = 0; i < TM; i++)
#pragma unroll
        for (int j = 0; j < TN; j++) acc[i][j] = 0.f;

    const int a_r = tid / 8;        // 0..31
    const int a_k = (tid % 8) * 4;  // 0..28

    constexpr int BTH = BN / 4;        // threads per k-row (32 or 16)
    constexpr int BKSTEP = 256 / BTH;  // 8 or 16
    const int b_k = tid / BTH;
    const int b_n = (tid % BTH) * 4;

    for (int k0 = 0; k0 < K; k0 += BK) {
#pragma unroll
        for (int it = 0; it < 4; it++) {
            int r = a_r + it * 32;
            int grow = row0 + r;
            float4 v = make_float4(0.f, 0.f, 0.f, 0.f);
            if (grow < M) v = *(const float4*)&A[grow * K + k0 + a_k];
            As[a_k + 0][r] = v.x;
            As[a_k + 1][r] = v.y;
            As[a_k + 2][r] = v.z;
            As[a_k + 3][r] = v.w;
        }
#pragma unroll
        for (int it = 0; it < BK / BKSTEP; it++) {
            int k = b_k + it * BKSTEP;
            *(float4*)&Bs[k][b_n] = *(const float4*)&W[(k0 + k) * BN + b_n];
        }
        __syncthreads();

#pragma unroll
        for (int kk = 0; kk < BK; kk++) {
            float a[TM];
#pragma unroll
            for (int i = 0; i < TM; i += 4) {
                float4 av = *(const float4*)&As[kk][ty * TM + i];
                a[i] = av.x; a[i + 1] = av.y; a[i + 2] = av.z; a[i + 3] = av.w;
            }
            float b[TN];
#pragma unroll
            for (int j = 0; j < TN; j += 4) {
                float4 bv = *(const float4*)&Bs[kk][tx * TN + j];
                b[j] = bv.x; b[j + 1] = bv.y; b[j + 2] = bv.z; b[j + 3] = bv.w;
            }
#pragma unroll
            for (int i = 0; i < TM; i++)
#pragma unroll
                for (int j = 0; j < TN; j++) acc[i][j] += a[i] * b[j];
        }
        __syncthreads();
    }

#pragma unroll
    for (int i = 0; i < TM; i++) {
        int row = row0 + ty * TM + i;
        if (row >= M) continue;
        float inv = 0.f;
        if (EPI) inv = 1.f / fmaxf(deg[row], 1.f);
#pragma unroll
        for (int j = 0; j < TN; j += 4) {
            int col = tx * TN + j;
            float4 o;
            float* po = (float*)&o;
#pragma unroll
            for (int q = 0; q < 4; q++) {
                float v = acc[i][j + q];
                if (EPI) v += agg[row * BN + col + q] * inv + bias[col + q];
                if (RELU) v = fmaxf(v, 0.f);
                po[q] = v;
            }
            *(float4*)&C[row * BN + col] = o;
        }
    }
}

// ---------------------------------------------------------------------------
extern "C" void kernel_launch(void* const* d_in, const int* in_sizes, int n_in,
                              void* d_out, int out_size) {
    const float* x       = (const float*)d_in[0];
    const int* ei        = (const int*)d_in[1];   // int32! (JAX x64 disabled)
    const float* Wl1     = (const float*)d_in[2];
    const float* Wr1     = (const float*)d_in[3];
    const float* b1      = (const float*)d_in[4];
    const float* Wl2     = (const float*)d_in[5];
    const float* Wr2     = (const float*)d_in[6];
    const float* b2      = (const float*)d_in[7];
    float* out           = (float*)d_out;

    const int M = in_sizes[0] / 128;  // n_nodes
    const int E = in_sizes[1] / 2;    // n_edges

    float *p_y, *p_agg1, *p_h, *p_z, *p_agg2, *p_deg;
    int *p_off, *p_csr;
    unsigned long long *p_keyA, *p_keyB;
    cudaGetSymbolAddress((void**)&p_y,    g_y);
    cudaGetSymbolAddress((void**)&p_agg1, g_agg1);
    cudaGetSymbolAddress((void**)&p_h,    g_h);
    cudaGetSymbolAddress((void**)&p_z,    g_z);
    cudaGetSymbolAddress((void**)&p_agg2, g_agg2);
    cudaGetSymbolAddress((void**)&p_deg,  g_deg);
    cudaGetSymbolAddress((void**)&p_off,  g_off);
    cudaGetSymbolAddress((void**)&p_csr,  g_csr_src);
    cudaGetSymbolAddress((void**)&p_keyA, g_keyA);
    cudaGetSymbolAddress((void**)&p_keyB, g_keyB);

    const int eb = (E + 255) / 256;

    // ---- CSR build: atomic-free deterministic merge sort ----
    init_keys_kernel<<<eb, 256>>>(ei, p_keyA, E);
    unsigned long long* bufs[2] = {p_keyA, p_keyB};
    int cur = 0;
    for (int W = 1; W < E; W <<= 1) {
        merge_pass_kernel<<<eb, 256>>>(bufs[cur], bufs[cur ^ 1], E, W);
        cur ^= 1;
    }
    const unsigned long long* sorted = bufs[cur];
    bounds_kernel<<<(M + 256) / 256, 256>>>(sorted, p_off, E, M);
    deg_kernel<<<(M + 255) / 256, 256>>>(p_off, p_deg, M);
    extract_kernel<<<eb, 256>>>(sorted, ei, p_csr, E);

    const int gemm_grid = (M + 127) / 128;

    // ---- Layer 1 ----
    gemm128<128, false, false><<<gemm_grid, 256>>>(x, Wl1, nullptr, nullptr,
                                                   nullptr, p_y, M);
    {
        int blocks = (M + 7) / 8;  // 1 node per warp, 8 warps per block
        gather_kernel<128><<<blocks, 256>>>(p_y, p_csr, p_off, p_agg1, M);
    }
    gemm128<128, true, true><<<gemm_grid, 256>>>(x, Wr1, p_agg1, p_deg, b1,
                                                 p_h, M);

    // ---- Layer 2 ----
    gemm128<64, false, false><<<gemm_grid, 256>>>(p_h, Wl2, nullptr, nullptr,
                                                  nullptr, p_z, M);
    {
        int blocks = (M + 15) / 16;  // 2 nodes per warp, 16 per block
        gather_kernel<64><<<blocks, 256>>>(p_z, p_csr, p_off, p_agg2, M);
    }
    gemm128<64, true, false><<<gemm_grid, 256>>>(p_h, Wr2, p_agg2, p_deg, b2,
                                                 out, M);
}